// round 15
// baseline (speedup 1.0000x reference)
#include <cuda_runtime.h>
#include <cuda_bf16.h>
#include <cuda_fp16.h>
#include <math.h>

// ---------------- problem constants ----------------
#define N1 160000
#define N2 40000
#define N3 10000
#define E1 800000
#define E2 200000
#define D1 256          // H1*HID
#define D2 64           // OUT
#define NEG_SLOPE 0.2f
#define BN_EPS 1e-5f
#define SM_EPS 1e-16f
#define FULLM 0xFFFFFFFFu

// ---------------- device scratch (allocation-free) ----------------
__device__ __half g_xl1h[(size_t)N1 * D1];   // 82 MB  fp16 gather table
__device__ float  g_xr1[(size_t)N2 * D1];    // 41 MB
__device__ __half g_hh [(size_t)N2 * D1];    // 20.5 MB (layer1 out, fp16, pre-BN)
__device__ float  g_xl2[(size_t)N2 * D2];    // 10.2 MB
__device__ float  g_xr2[(size_t)N3 * D2];    // 2.6 MB

__device__ __half g_w1lt[D1 * 128];          // [N=256][K=128]
__device__ __half g_w1rt[D1 * 128];
__device__ __half g_w2lt[D2 * D1];           // [N=64][K=256]
__device__ __half g_w2rt[D2 * D1];

__device__ int g_cnt1[N2];
__device__ int g_rp1 [N2 + 1];
__device__ int g_cur1[N2];
__device__ int g_csr1[E1];

__device__ int g_cnt2[N3];
__device__ int g_rp2 [N3 + 1];
__device__ int g_cur2[N3];
__device__ int g_csr2[E2];

__device__ float g_bn_sum[D1];
__device__ float g_bn_sqs[D1];
__device__ float g_bn_scale[D1];
__device__ float g_bn_shift[D1];

__device__ __forceinline__ float lrelu(float v) { return v > 0.f ? v : NEG_SLOPE * v; }

__device__ __forceinline__ void unpack8(uint4 r, float* f) {
    float2 a = __half22float2(*reinterpret_cast<const __half2*>(&r.x));
    float2 b = __half22float2(*reinterpret_cast<const __half2*>(&r.y));
    float2 c = __half22float2(*reinterpret_cast<const __half2*>(&r.z));
    float2 d = __half22float2(*reinterpret_cast<const __half2*>(&r.w));
    f[0] = a.x; f[1] = a.y; f[2] = b.x; f[3] = b.y;
    f[4] = c.x; f[5] = c.y; f[6] = d.x; f[7] = d.y;
}

// ---------------- CSR build ----------------
__global__ void zero_kernel() {
    int i = blockIdx.x * blockDim.x + threadIdx.x;
    if (i < N2) g_cnt1[i] = 0;
    if (i < N3) g_cnt2[i] = 0;
    if (i < D1) { g_bn_sum[i] = 0.f; g_bn_sqs[i] = 0.f; }
}

__global__ void hist_kernel(const int* __restrict__ d1, const int* __restrict__ d2) {
    int i = (blockIdx.x * blockDim.x + threadIdx.x) * 4;
    if (i < E1) {
        int4 v = *(const int4*)(d1 + i);
        atomicAdd(&g_cnt1[v.x], 1); atomicAdd(&g_cnt1[v.y], 1);
        atomicAdd(&g_cnt1[v.z], 1); atomicAdd(&g_cnt1[v.w], 1);
    }
    if (i < E2) {
        int4 v = *(const int4*)(d2 + i);
        atomicAdd(&g_cnt2[v.x], 1); atomicAdd(&g_cnt2[v.y], 1);
        atomicAdd(&g_cnt2[v.z], 1); atomicAdd(&g_cnt2[v.w], 1);
    }
}

__global__ __launch_bounds__(1024) void scan2_kernel() {
    int which = blockIdx.x;
    const int* cnt = which ? g_cnt2 : g_cnt1;
    int* rp  = which ? g_rp2  : g_rp1;
    int* cur = which ? g_cur2 : g_cur1;
    int n    = which ? N3     : N2;

    __shared__ int wsum[32];
    __shared__ int carry;
    int tid = threadIdx.x;
    int lane = tid & 31, wid = tid >> 5;
    if (tid == 0) carry = 0;
    __syncthreads();

    for (int base = 0; base < n; base += 4096) {
        int i0 = base + tid * 4;
        int v0 = (i0 + 0 < n) ? cnt[i0 + 0] : 0;
        int v1 = (i0 + 1 < n) ? cnt[i0 + 1] : 0;
        int v2 = (i0 + 2 < n) ? cnt[i0 + 2] : 0;
        int v3 = (i0 + 3 < n) ? cnt[i0 + 3] : 0;
        int tot = v0 + v1 + v2 + v3;
        int isum = tot;
        #pragma unroll
        for (int off = 1; off < 32; off <<= 1) {
            int t = __shfl_up_sync(FULLM, isum, off);
            if (lane >= off) isum += t;
        }
        if (lane == 31) wsum[wid] = isum;
        __syncthreads();
        if (wid == 0) {
            int s = wsum[lane];
            #pragma unroll
            for (int off = 1; off < 32; off <<= 1) {
                int t = __shfl_up_sync(FULLM, s, off);
                if (lane >= off) s += t;
            }
            wsum[lane] = s;
        }
        __syncthreads();
        int carryv = carry;
        int woff = (wid > 0) ? wsum[wid - 1] : 0;
        int excl = carryv + woff + (isum - tot);
        if (i0 + 0 < n) { rp[i0 + 0] = excl;                cur[i0 + 0] = excl; }
        if (i0 + 1 < n) { rp[i0 + 1] = excl + v0;           cur[i0 + 1] = excl + v0; }
        if (i0 + 2 < n) { rp[i0 + 2] = excl + v0 + v1;      cur[i0 + 2] = excl + v0 + v1; }
        if (i0 + 3 < n) { rp[i0 + 3] = excl + v0 + v1 + v2; cur[i0 + 3] = excl + v0 + v1 + v2; }
        __syncthreads();
        if (tid == 0) carry = carryv + wsum[31];
        __syncthreads();
    }
    if (tid == 0) rp[n] = carry;
}

__global__ void scatter_kernel(const int* __restrict__ src1, const int* __restrict__ dst1,
                               const int* __restrict__ src2, const int* __restrict__ dst2) {
    int e = (blockIdx.x * blockDim.x + threadIdx.x) * 4;
    if (e < E1) {
        int4 s = *(const int4*)(src1 + e);
        int4 d = *(const int4*)(dst1 + e);
        int p;
        p = atomicAdd(&g_cur1[d.x], 1); g_csr1[p] = s.x;
        p = atomicAdd(&g_cur1[d.y], 1); g_csr1[p] = s.y;
        p = atomicAdd(&g_cur1[d.z], 1); g_csr1[p] = s.z;
        p = atomicAdd(&g_cur1[d.w], 1); g_csr1[p] = s.w;
    }
    if (e < E2) {
        int4 s = *(const int4*)(src2 + e);
        int4 d = *(const int4*)(dst2 + e);
        int p;
        p = atomicAdd(&g_cur2[d.x], 1); g_csr2[p] = s.x;
        p = atomicAdd(&g_cur2[d.y], 1); g_csr2[p] = s.y;
        p = atomicAdd(&g_cur2[d.z], 1); g_csr2[p] = s.z;
        p = atomicAdd(&g_cur2[d.w], 1); g_csr2[p] = s.w;
    }
}

__global__ void cvt_w_kernel(const float* __restrict__ W1l, const float* __restrict__ W1r,
                             const float* __restrict__ W2l, const float* __restrict__ W2r) {
    int i = blockIdx.x * blockDim.x + threadIdx.x;
    if (i < 128 * 256) {
        int k = i >> 8, n = i & 255;
        g_w1lt[n * 128 + k] = __float2half(W1l[i]);
        g_w1rt[n * 128 + k] = __float2half(W1r[i]);
    }
    if (i < 256 * 64) {
        int k = i >> 6, n = i & 63;
        g_w2lt[n * 256 + k] = __float2half(W2l[i]);
        g_w2rt[n * 256 + k] = __float2half(W2r[i]);
    }
}

// ---------------- mma + ldmatrix helpers ----------------
__device__ __forceinline__ void mma_f16(float* d, const unsigned* a, const unsigned* b) {
    asm volatile("mma.sync.aligned.m16n8k16.row.col.f32.f16.f16.f32 "
        "{%0,%1,%2,%3}, {%4,%5,%6,%7}, {%8,%9}, {%0,%1,%2,%3};"
        : "+f"(d[0]), "+f"(d[1]), "+f"(d[2]), "+f"(d[3])
        : "r"(a[0]), "r"(a[1]), "r"(a[2]), "r"(a[3]), "r"(b[0]), "r"(b[1]));
}

__device__ __forceinline__ void ldsm_x4(unsigned& r0, unsigned& r1, unsigned& r2, unsigned& r3,
                                        unsigned addr) {
    asm volatile("ldmatrix.sync.aligned.m8n8.x4.shared.b16 {%0,%1,%2,%3}, [%4];"
        : "=r"(r0), "=r"(r1), "=r"(r2), "=r"(r3) : "r"(addr));
}

__device__ __forceinline__ uint4 pack_f8_to_h8(float4 v0, float4 v1) {
    __half2 h0 = __floats2half2_rn(v0.x, v0.y);
    __half2 h1 = __floats2half2_rn(v0.z, v0.w);
    __half2 h2 = __floats2half2_rn(v1.x, v1.y);
    __half2 h3 = __floats2half2_rn(v1.z, v1.w);
    uint4 u;
    u.x = *(unsigned*)&h0; u.y = *(unsigned*)&h1;
    u.z = *(unsigned*)&h2; u.w = *(unsigned*)&h3;
    return u;
}

// ---------------- layer-1 GEMM: C[M,256] = A_fp32[M,128] @ Bt[256,128]^T + bias ----------------
// BM=64, full N=256, BK=32, 256 threads (8 warps: 2M x 4N), warp tile 32x64.
__global__ __launch_bounds__(256, 2) void gemm_f16_l1(
    const float* __restrict__ A, const __half* __restrict__ Bt,
    const float* __restrict__ bias, void* __restrict__ Cout,
    int M, int out_half)
{
    __shared__ __half As[64][40];
    __shared__ __half Bs[256][40];
    const int K = 128;
    int tid = threadIdx.x;
    int lane = tid & 31, warp = tid >> 5;
    int wm = warp & 1, wn = warp >> 1;
    int g = lane >> 2, t = lane & 3;
    int bm = blockIdx.x * 64;

    int arow = tid >> 2, aseg = (tid & 3) * 8;

    unsigned asBase = (unsigned)__cvta_generic_to_shared(&As[0][0]);
    unsigned bsBase = (unsigned)__cvta_generic_to_shared(&Bs[0][0]);
    unsigned aAddr[2];
    #pragma unroll
    for (int mi = 0; mi < 2; mi++)
        aAddr[mi] = asBase + (unsigned)((wm * 32 + mi * 16 + (lane & 15)) * 80 + ((lane >> 4) * 8) * 2);
    unsigned bAddr[4];
    #pragma unroll
    for (int p = 0; p < 4; p++)
        bAddr[p] = bsBase + (unsigned)((wn * 64 + p * 16 + ((lane >> 4) << 3) + (lane & 7)) * 80
                                       + (((lane >> 3) & 1) * 8) * 2);

    float acc[2][8][4];
    #pragma unroll
    for (int mi = 0; mi < 2; mi++)
        #pragma unroll
        for (int ni = 0; ni < 8; ni++)
            #pragma unroll
            for (int j = 0; j < 4; j++) acc[mi][ni][j] = 0.f;

    float4 va0 = make_float4(0.f, 0.f, 0.f, 0.f), va1 = va0;
    uint4 vb[4];
    {
        int gr = bm + arow;
        if (gr < M) {
            const float* ap = A + (size_t)gr * K + aseg;
            va0 = *(const float4*)ap;
            va1 = *(const float4*)(ap + 4);
        }
        #pragma unroll
        for (int p = 0; p < 4; p++) {
            int idx = tid + p * 256;
            vb[p] = *(const uint4*)(Bt + (size_t)(idx >> 2) * K + (idx & 3) * 8);
        }
    }

    for (int k0 = 0; k0 < K; k0 += 32) {
        *(uint4*)&As[arow][aseg] = pack_f8_to_h8(va0, va1);
        #pragma unroll
        for (int p = 0; p < 4; p++) {
            int idx = tid + p * 256;
            *(uint4*)&Bs[idx >> 2][(idx & 3) * 8] = vb[p];
        }
        __syncthreads();

        if (k0 + 32 < K) {
            int gr = bm + arow;
            va0 = make_float4(0.f, 0.f, 0.f, 0.f); va1 = va0;
            if (gr < M) {
                const float* ap = A + (size_t)gr * K + k0 + 32 + aseg;
                va0 = *(const float4*)ap;
                va1 = *(const float4*)(ap + 4);
            }
            #pragma unroll
            for (int p = 0; p < 4; p++) {
                int idx = tid + p * 256;
                vb[p] = *(const uint4*)(Bt + (size_t)(idx >> 2) * K + k0 + 32 + (idx & 3) * 8);
            }
        }

        #pragma unroll
        for (int kk = 0; kk < 32; kk += 16) {
            unsigned af[2][4], bf[8][2];
            #pragma unroll
            for (int mi = 0; mi < 2; mi++)
                ldsm_x4(af[mi][0], af[mi][1], af[mi][2], af[mi][3], aAddr[mi] + kk * 2);
            #pragma unroll
            for (int p = 0; p < 4; p++)
                ldsm_x4(bf[2 * p][0], bf[2 * p][1], bf[2 * p + 1][0], bf[2 * p + 1][1],
                        bAddr[p] + kk * 2);
            #pragma unroll
            for (int mi = 0; mi < 2; mi++)
                #pragma unroll
                for (int ni = 0; ni < 8; ni++)
                    mma_f16(acc[mi][ni], af[mi], bf[ni]);
        }
        __syncthreads();
    }

    #pragma unroll
    for (int mi = 0; mi < 2; mi++) {
        #pragma unroll
        for (int ni = 0; ni < 8; ni++) {
            int col = wn * 64 + ni * 8 + 2 * t;
            float2 bb = *(const float2*)(bias + col);
            int r0 = bm + wm * 32 + mi * 16 + g;
            int r1 = r0 + 8;
            if (out_half) {
                __half* C = (__half*)Cout;
                if (r0 < M)
                    *(__half2*)(C + (size_t)r0 * 256 + col) =
                        __floats2half2_rn(acc[mi][ni][0] + bb.x, acc[mi][ni][1] + bb.y);
                if (r1 < M)
                    *(__half2*)(C + (size_t)r1 * 256 + col) =
                        __floats2half2_rn(acc[mi][ni][2] + bb.x, acc[mi][ni][3] + bb.y);
            } else {
                float* C = (float*)Cout;
                if (r0 < M)
                    *(float2*)(C + (size_t)r0 * 256 + col) =
                        make_float2(acc[mi][ni][0] + bb.x, acc[mi][ni][1] + bb.y);
                if (r1 < M)
                    *(float2*)(C + (size_t)r1 * 256 + col) =
                        make_float2(acc[mi][ni][2] + bb.x, acc[mi][ni][3] + bb.y);
            }
        }
    }
}

// ---------------- layer-2 GEMM: C[M,64] = relu(bn(Ah[M,256])) @ Bt[64,256]^T + bias ----------------
// A is fp16 (g_hh); BN+ReLU applied during staging.
__global__ __launch_bounds__(256) void gemm_f16_l2(
    const __half* __restrict__ A, const __half* __restrict__ Bt,
    const float* __restrict__ bias, float* __restrict__ C, int M)
{
    __shared__ __half As[128][40];
    __shared__ __half Bs[64][40];
    const int K = 256;
    int tid = threadIdx.x;
    int lane = tid & 31, warp = tid >> 5;
    int wm = warp & 3, wn = warp >> 2;
    int g = lane >> 2, t = lane & 3;
    int bm = blockIdx.x * 128;

    unsigned asBase = (unsigned)__cvta_generic_to_shared(&As[0][0]);
    unsigned bsBase = (unsigned)__cvta_generic_to_shared(&Bs[0][0]);
    unsigned aAddr[2];
    #pragma unroll
    for (int mi = 0; mi < 2; mi++)
        aAddr[mi] = asBase + (unsigned)((wm * 32 + mi * 16 + (lane & 15)) * 80 + ((lane >> 4) * 8) * 2);
    unsigned bAddr[2];
    #pragma unroll
    for (int p = 0; p < 2; p++)
        bAddr[p] = bsBase + (unsigned)((wn * 32 + p * 16 + ((lane >> 4) << 3) + (lane & 7)) * 80
                                       + (((lane >> 3) & 1) * 8) * 2);

    float acc[2][4][4];
    #pragma unroll
    for (int mi = 0; mi < 2; mi++)
        #pragma unroll
        for (int ni = 0; ni < 4; ni++)
            #pragma unroll
            for (int j = 0; j < 4; j++) acc[mi][ni][j] = 0.f;

    for (int k0 = 0; k0 < K; k0 += 32) {
        // A tile 128 rows x 32 halves = 512 uint4 segments -> 2 passes of 256 threads
        #pragma unroll
        for (int p = 0; p < 2; p++) {
            int idx = tid + p * 256;          // 0..511
            int row = idx >> 2;               // 0..127
            int segq = (idx & 3) * 8;         // 0,8,16,24
            int gr = bm + row;
            uint4 raw = make_uint4(0u, 0u, 0u, 0u);
            if (gr < M) raw = *(const uint4*)(A + (size_t)gr * K + k0 + segq);
            float f[8]; unpack8(raw, f);
            float4 sc0 = *(const float4*)(g_bn_scale + k0 + segq);
            float4 sc1 = *(const float4*)(g_bn_scale + k0 + segq + 4);
            float4 sh0 = *(const float4*)(g_bn_shift + k0 + segq);
            float4 sh1 = *(const float4*)(g_bn_shift + k0 + segq + 4);
            float4 v0 = make_float4(fmaxf(f[0] * sc0.x + sh0.x, 0.f),
                                    fmaxf(f[1] * sc0.y + sh0.y, 0.f),
                                    fmaxf(f[2] * sc0.z + sh0.z, 0.f),
                                    fmaxf(f[3] * sc0.w + sh0.w, 0.f));
            float4 v1 = make_float4(fmaxf(f[4] * sc1.x + sh1.x, 0.f),
                                    fmaxf(f[5] * sc1.y + sh1.y, 0.f),
                                    fmaxf(f[6] * sc1.z + sh1.z, 0.f),
                                    fmaxf(f[7] * sc1.w + sh1.w, 0.f));
            *(uint4*)&As[row][segq] = pack_f8_to_h8(v0, v1);
        }
        {
            int row = tid >> 2, seg = (tid & 3) * 8;
            *(uint4*)&Bs[row][seg] = *(const uint4*)(Bt + (size_t)row * K + k0 + seg);
        }
        __syncthreads();
        #pragma unroll
        for (int kk = 0; kk < 32; kk += 16) {
            unsigned af[2][4], bf[4][2];
            #pragma unroll
            for (int mi = 0; mi < 2; mi++)
                ldsm_x4(af[mi][0], af[mi][1], af[mi][2], af[mi][3], aAddr[mi] + kk * 2);
            #pragma unroll
            for (int p = 0; p < 2; p++)
                ldsm_x4(bf[2 * p][0], bf[2 * p][1], bf[2 * p + 1][0], bf[2 * p + 1][1],
                        bAddr[p] + kk * 2);
            #pragma unroll
            for (int mi = 0; mi < 2; mi++)
                #pragma unroll
                for (int ni = 0; ni < 4; ni++)
                    mma_f16(acc[mi][ni], af[mi], bf[ni]);
        }
        __syncthreads();
    }

    #pragma unroll
    for (int mi = 0; mi < 2; mi++) {
        #pragma unroll
        for (int ni = 0; ni < 4; ni++) {
            int col = wn * 32 + ni * 8 + 2 * t;
            float2 bb = *(const float2*)(bias + col);
            int r0 = bm + wm * 32 + mi * 16 + g;
            int r1 = r0 + 8;
            if (r0 < M)
                *(float2*)(C + (size_t)r0 * 64 + col) =
                    make_float2(acc[mi][ni][0] + bb.x, acc[mi][ni][1] + bb.y);
            if (r1 < M)
                *(float2*)(C + (size_t)r1 * 64 + col) =
                    make_float2(acc[mi][ni][2] + bb.x, acc[mi][ni][3] + bb.y);
        }
    }
}

// ---------------- layer-1 fused edge kernel: 8-edge groups + fused BN stats ----------------
__global__ __launch_bounds__(256) void edge1_kernel(const float* __restrict__ att,
                                                    const float* __restrict__ bias)
{
    int w = (blockIdx.x * 256 + threadIdx.x) >> 5;
    int lane = threadIdx.x & 31;
    if (w >= N2) return;
    int off = lane * 8;

    float xr[8], at[8];
    {
        const float* xrp = g_xr1 + (size_t)w * D1 + off;
        float4 a = *(const float4*)xrp, b = *(const float4*)(xrp + 4);
        xr[0] = a.x; xr[1] = a.y; xr[2] = a.z; xr[3] = a.w;
        xr[4] = b.x; xr[5] = b.y; xr[6] = b.z; xr[7] = b.w;
        float4 c = *(const float4*)(att + off), d = *(const float4*)(att + off + 4);
        at[0] = c.x; at[1] = c.y; at[2] = c.z; at[3] = c.w;
        at[4] = d.x; at[5] = d.y; at[6] = d.z; at[7] = d.w;
    }

    float m = -INFINITY, s = 0.f;
    float ac[8] = {0.f, 0.f, 0.f, 0.f, 0.f, 0.f, 0.f, 0.f};

    int jb = g_rp1[w], je = g_rp1[w + 1];
    int j = jb;

    for (; j + 8 <= je; j += 8) {
        uint4 rr[8];
        #pragma unroll
        for (int q = 0; q < 8; q++) {
            int src = __ldg(g_csr1 + j + q);
            rr[q] = __ldg((const uint4*)(g_xl1h + (size_t)src * D1 + off));
        }
        float p[8];
        #pragma unroll
        for (int q = 0; q < 8; q++) {
            float f[8]; unpack8(rr[q], f);
            float pp = 0.f;
            #pragma unroll
            for (int c = 0; c < 8; c++) pp += lrelu(f[c] + xr[c]) * at[c];
            pp += __shfl_xor_sync(FULLM, pp, 1);
            pp += __shfl_xor_sync(FULLM, pp, 2);
            pp += __shfl_xor_sync(FULLM, pp, 4);
            p[q] = pp;
        }
        float nm = m;
        #pragma unroll
        for (int q = 0; q < 8; q++) nm = fmaxf(nm, p[q]);
        float sc = __expf(m - nm);
        float wq[8], ssum = 0.f;
        #pragma unroll
        for (int q = 0; q < 8; q++) { wq[q] = __expf(p[q] - nm); ssum += wq[q]; }
        s = s * sc + ssum;
        #pragma unroll
        for (int c = 0; c < 8; c++) ac[c] *= sc;
        #pragma unroll
        for (int q = 0; q < 8; q++) {
            float f[8]; unpack8(rr[q], f);
            #pragma unroll
            for (int c = 0; c < 8; c++) ac[c] += wq[q] * f[c];
        }
        m = nm;
    }

    for (; j + 4 <= je; j += 4) {
        uint4 rr[4];
        #pragma unroll
        for (int q = 0; q < 4; q++) {
            int src = __ldg(g_csr1 + j + q);
            rr[q] = __ldg((const uint4*)(g_xl1h + (size_t)src * D1 + off));
        }
        float p[4];
        #pragma unroll
        for (int q = 0; q < 4; q++) {
            float f[8]; unpack8(rr[q], f);
            float pp = 0.f;
            #pragma unroll
            for (int c = 0; c < 8; c++) pp += lrelu(f[c] + xr[c]) * at[c];
            pp += __shfl_xor_sync(FULLM, pp, 1);
            pp += __shfl_xor_sync(FULLM, pp, 2);
            pp += __shfl_xor_sync(FULLM, pp, 4);
            p[q] = pp;
        }
        float nm = fmaxf(fmaxf(fmaxf(p[0], p[1]), fmaxf(p[2], p[3])), m);
        float sc = __expf(m - nm);
        float wq[4], ssum = 0.f;
        #pragma unroll
        for (int q = 0; q < 4; q++) { wq[q] = __expf(p[q] - nm); ssum += wq[q]; }
        s = s * sc + ssum;
        #pragma unroll
        for (int c = 0; c < 8; c++) ac[c] *= sc;
        #pragma unroll
        for (int q = 0; q < 4; q++) {
            float f[8]; unpack8(rr[q], f);
            #pragma unroll
            for (int c = 0; c < 8; c++) ac[c] += wq[q] * f[c];
        }
        m = nm;
    }

    for (; j < je; ++j) {
        int src = __ldg(g_csr1 + j);
        uint4 raw = __ldg((const uint4*)(g_xl1h + (size_t)src * D1 + off));
        float f[8]; unpack8(raw, f);
        float pp = 0.f;
        #pragma unroll
        for (int c = 0; c < 8; c++) pp += lrelu(f[c] + xr[c]) * at[c];
        pp += __shfl_xor_sync(FULLM, pp, 1);
        pp += __shfl_xor_sync(FULLM, pp, 2);
        pp += __shfl_xor_sync(FULLM, pp, 4);
        float nm = fmaxf(m, pp);
        float sc = __expf(m - nm);
        float wg = __expf(pp - nm);
        s = s * sc + wg;
        #pragma unroll
        for (int c = 0; c < 8; c++) ac[c] = ac[c] * sc + wg * f[c];
        m = nm;
    }

    float inv = 1.f / (s + SM_EPS);
    float o[8];
    {
        float4 bA = *(const float4*)(bias + off);
        float4 bB = *(const float4*)(bias + off + 4);
        o[0] = ac[0] * inv + bA.x; o[1] = ac[1] * inv + bA.y;
        o[2] = ac[2] * inv + bA.z; o[3] = ac[3] * inv + bA.w;
        o[4] = ac[4] * inv + bB.x; o[5] = ac[5] * inv + bB.y;
        o[6] = ac[6] * inv + bB.z; o[7] = ac[7] * inv + bB.w;
    }

    // fused BN statistics (replaces the bn_stats pass)
    #pragma unroll
    for (int c = 0; c < 8; c++) {
        atomicAdd(&g_bn_sum[off + c], o[c]);
        atomicAdd(&g_bn_sqs[off + c], o[c] * o[c]);
    }

    // fp16 store
    uint4 packed = pack_f8_to_h8(make_float4(o[0], o[1], o[2], o[3]),
                                 make_float4(o[4], o[5], o[6], o[7]));
    *(uint4*)(g_hh + (size_t)w * D1 + off) = packed;
}

// ---------------- batchnorm finalize ----------------
__global__ void bn_final_kernel(const float* __restrict__ gamma, const float* __restrict__ beta) {
    int c = threadIdx.x;
    float mu = g_bn_sum[c] * (1.f / N2);
    float var = g_bn_sqs[c] * (1.f / N2) - mu * mu;
    var = fmaxf(var, 0.f);
    float sc = gamma[c] * rsqrtf(var + BN_EPS);
    g_bn_scale[c] = sc;
    g_bn_shift[c] = beta[c] - mu * sc;
}

// ---------------- layer-2 fused edge kernel + log_softmax ----------------
__global__ __launch_bounds__(256) void edge2_kernel(const float* __restrict__ att,
                                                    const float* __restrict__ bias,
                                                    float* __restrict__ out)
{
    int w = (blockIdx.x * 256 + threadIdx.x) >> 5;
    int lane = threadIdx.x & 31;
    if (w >= N3) return;
    int off = lane * 2;

    float2 xr = *(const float2*)(g_xr2 + (size_t)w * D2 + off);
    float2 at = *(const float2*)(att + off);
    float m = -INFINITY, s = 0.f, a0 = 0.f, a1 = 0.f;

    int jb = g_rp2[w], je = g_rp2[w + 1];
    for (int j = jb; j < je; ++j) {
        int src = g_csr2[j];
        float2 xj = *(const float2*)(g_xl2 + (size_t)src * D2 + off);
        float p = lrelu(xj.x + xr.x) * at.x + lrelu(xj.y + xr.y) * at.y;
        #pragma unroll
        for (int o = 16; o > 0; o >>= 1) p += __shfl_xor_sync(FULLM, p, o);
        float nm = fmaxf(m, p);
        float sc = __expf(m - nm);
        float wg = __expf(p - nm);
        s = s * sc + wg;
        a0 = a0 * sc + wg * xj.x;
        a1 = a1 * sc + wg * xj.y;
        m = nm;
    }
    float inv = 1.f / (s + SM_EPS);
    float o0 = a0 * inv + bias[off];
    float o1 = a1 * inv + bias[off + 1];

    float mx = fmaxf(o0, o1);
    #pragma unroll
    for (int o = 16; o > 0; o >>= 1) mx = fmaxf(mx, __shfl_xor_sync(FULLM, mx, o));
    float se = __expf(o0 - mx) + __expf(o1 - mx);
    #pragma unroll
    for (int o = 16; o > 0; o >>= 1) se += __shfl_xor_sync(FULLM, se, o);
    float lse = __logf(se);
    float2 r = make_float2(o0 - mx - lse, o1 - mx - lse);
    *(float2*)(out + (size_t)w * D2 + off) = r;
}

// ---------------- launch ----------------
extern "C" void kernel_launch(void* const* d_in, const int* in_sizes, int n_in,
                              void* d_out, int out_size)
{
    const float* x       = (const float*)d_in[0];
    const int*   ei1_src = (const int*)d_in[1];
    const int*   ei1_dst = (const int*)d_in[2];
    const int*   ei2_src = (const int*)d_in[3];
    const int*   ei2_dst = (const int*)d_in[4];
    const float* W1l     = (const float*)d_in[5];
    const float* b1l     = (const float*)d_in[6];
    const float* W1r     = (const float*)d_in[7];
    const float* b1r     = (const float*)d_in[8];
    const float* att1    = (const float*)d_in[9];
    const float* bias1   = (const float*)d_in[10];
    const float* gamma   = (const float*)d_in[11];
    const float* beta    = (const float*)d_in[12];
    const float* W2l     = (const float*)d_in[13];
    const float* b2l     = (const float*)d_in[14];
    const float* W2r     = (const float*)d_in[15];
    const float* b2r     = (const float*)d_in[16];
    const float* att2    = (const float*)d_in[17];
    const float* bias2   = (const float*)d_in[18];
    float* out = (float*)d_out;

    __half *p_xl1h, *p_hh, *p_w1lt, *p_w1rt, *p_w2lt, *p_w2rt;
    float *p_xr1, *p_xl2, *p_xr2;
    cudaGetSymbolAddress((void**)&p_xl1h, g_xl1h);
    cudaGetSymbolAddress((void**)&p_hh,   g_hh);
    cudaGetSymbolAddress((void**)&p_w1lt, g_w1lt);
    cudaGetSymbolAddress((void**)&p_w1rt, g_w1rt);
    cudaGetSymbolAddress((void**)&p_w2lt, g_w2lt);
    cudaGetSymbolAddress((void**)&p_w2rt, g_w2rt);
    cudaGetSymbolAddress((void**)&p_xr1, g_xr1);
    cudaGetSymbolAddress((void**)&p_xl2, g_xl2);
    cudaGetSymbolAddress((void**)&p_xr2, g_xr2);

    // fork side stream for the CSR chain (capturable event-fork pattern)
    cudaStream_t s2;
    cudaStreamCreateWithFlags(&s2, cudaStreamNonBlocking);
    cudaEvent_t evF, evJ;
    cudaEventCreateWithFlags(&evF, cudaEventDisableTiming);
    cudaEventCreateWithFlags(&evJ, cudaEventDisableTiming);

    cudaEventRecord(evF, 0);
    cudaStreamWaitEvent(s2, evF, 0);

    // Submission order keeps gemm_f16_l1(N1) as the 4th kernel for ncu capture.
    zero_kernel<<<(N2 + 255) / 256, 256, 0, s2>>>();
    hist_kernel<<<(E1 / 4 + 255) / 256, 256, 0, s2>>>(ei1_dst, ei2_dst);

    cvt_w_kernel<<<(128 * 256 + 255) / 256, 256>>>(W1l, W1r, W2l, W2r);
    gemm_f16_l1<<<N1 / 64, 256>>>(x, p_w1lt, b1l, p_xl1h, N1, 1);

    scan2_kernel<<<2, 1024, 0, s2>>>();
    scatter_kernel<<<(E1 / 4 + 255) / 256, 256, 0, s2>>>(ei1_src, ei1_dst, ei2_src, ei2_dst);
    cudaEventRecord(evJ, s2);

    gemm_f16_l1<<<(N2 + 63) / 64, 256>>>(x, p_w1rt, b1r, p_xr1, N2, 0);

    cudaStreamWaitEvent(0, evJ, 0);

    edge1_kernel<<<(N2 * 32 + 255) / 256, 256>>>(att1, bias1);

    bn_final_kernel<<<1, 256>>>(gamma, beta);

    gemm_f16_l2<<<(N2 + 127) / 128, 256>>>(p_hh, p_w2lt, b2l, p_xl2, N2);
    gemm_f16_l2<<<(N3 + 127) / 128, 256>>>(p_hh, p_w2rt, b2r, p_xr2, N3);

    edge2_kernel<<<(N3 * 32 + 255) / 256, 256>>>(att2, bias2, out);
}

// round 16
// speedup vs baseline: 9.1431x; 9.1431x over previous
#include <cuda_runtime.h>
#include <cuda_bf16.h>
#include <cuda_fp16.h>
#include <math.h>

// ---------------- problem constants ----------------
#define N1 160000
#define N2 40000
#define N3 10000
#define E1 800000
#define E2 200000
#define D1 256          // H1*HID
#define D2 64           // OUT
#define NEG_SLOPE 0.2f
#define BN_EPS 1e-5f
#define SM_EPS 1e-16f
#define FULLM 0xFFFFFFFFu

// ---------------- device scratch (allocation-free) ----------------
__device__ __half g_xl1h[(size_t)N1 * D1];   // 82 MB  fp16 gather table
__device__ float  g_xr1[(size_t)N2 * D1];    // 41 MB
__device__ __half g_hh [(size_t)N2 * D1];    // 20.5 MB (layer1 out, fp16, pre-BN)
__device__ float  g_xl2[(size_t)N2 * D2];    // 10.2 MB
__device__ float  g_xr2[(size_t)N3 * D2];    // 2.6 MB

__device__ __half g_w1lt[D1 * 128];          // [N=256][K=128]
__device__ __half g_w1rt[D1 * 128];
__device__ __half g_w2lt[D2 * D1];           // [N=64][K=256]
__device__ __half g_w2rt[D2 * D1];

__device__ int g_cnt1[N2];
__device__ int g_rp1 [N2 + 1];
__device__ int g_cur1[N2];
__device__ int g_csr1[E1];

__device__ int g_cnt2[N3];
__device__ int g_rp2 [N3 + 1];
__device__ int g_cur2[N3];
__device__ int g_csr2[E2];

__device__ float g_bn_sum[D1];
__device__ float g_bn_sqs[D1];
__device__ float g_bn_scale[D1];
__device__ float g_bn_shift[D1];

__device__ __forceinline__ float lrelu(float v) { return v > 0.f ? v : NEG_SLOPE * v; }

__device__ __forceinline__ void unpack8(uint4 r, float* f) {
    float2 a = __half22float2(*reinterpret_cast<const __half2*>(&r.x));
    float2 b = __half22float2(*reinterpret_cast<const __half2*>(&r.y));
    float2 c = __half22float2(*reinterpret_cast<const __half2*>(&r.z));
    float2 d = __half22float2(*reinterpret_cast<const __half2*>(&r.w));
    f[0] = a.x; f[1] = a.y; f[2] = b.x; f[3] = b.y;
    f[4] = c.x; f[5] = c.y; f[6] = d.x; f[7] = d.y;
}

// ---------------- CSR build ----------------
__global__ void zero_kernel() {
    int i = blockIdx.x * blockDim.x + threadIdx.x;
    if (i < N2) g_cnt1[i] = 0;
    if (i < N3) g_cnt2[i] = 0;
    if (i < D1) { g_bn_sum[i] = 0.f; g_bn_sqs[i] = 0.f; }
}

__global__ void hist_kernel(const int* __restrict__ d1, const int* __restrict__ d2) {
    int i = (blockIdx.x * blockDim.x + threadIdx.x) * 4;
    if (i < E1) {
        int4 v = *(const int4*)(d1 + i);
        atomicAdd(&g_cnt1[v.x], 1); atomicAdd(&g_cnt1[v.y], 1);
        atomicAdd(&g_cnt1[v.z], 1); atomicAdd(&g_cnt1[v.w], 1);
    }
    if (i < E2) {
        int4 v = *(const int4*)(d2 + i);
        atomicAdd(&g_cnt2[v.x], 1); atomicAdd(&g_cnt2[v.y], 1);
        atomicAdd(&g_cnt2[v.z], 1); atomicAdd(&g_cnt2[v.w], 1);
    }
}

__global__ __launch_bounds__(1024) void scan2_kernel() {
    int which = blockIdx.x;
    const int* cnt = which ? g_cnt2 : g_cnt1;
    int* rp  = which ? g_rp2  : g_rp1;
    int* cur = which ? g_cur2 : g_cur1;
    int n    = which ? N3     : N2;

    __shared__ int wsum[32];
    __shared__ int carry;
    int tid = threadIdx.x;
    int lane = tid & 31, wid = tid >> 5;
    if (tid == 0) carry = 0;
    __syncthreads();

    for (int base = 0; base < n; base += 4096) {
        int i0 = base + tid * 4;
        int v0 = (i0 + 0 < n) ? cnt[i0 + 0] : 0;
        int v1 = (i0 + 1 < n) ? cnt[i0 + 1] : 0;
        int v2 = (i0 + 2 < n) ? cnt[i0 + 2] : 0;
        int v3 = (i0 + 3 < n) ? cnt[i0 + 3] : 0;
        int tot = v0 + v1 + v2 + v3;
        int isum = tot;
        #pragma unroll
        for (int off = 1; off < 32; off <<= 1) {
            int t = __shfl_up_sync(FULLM, isum, off);
            if (lane >= off) isum += t;
        }
        if (lane == 31) wsum[wid] = isum;
        __syncthreads();
        if (wid == 0) {
            int s = wsum[lane];
            #pragma unroll
            for (int off = 1; off < 32; off <<= 1) {
                int t = __shfl_up_sync(FULLM, s, off);
                if (lane >= off) s += t;
            }
            wsum[lane] = s;
        }
        __syncthreads();
        int carryv = carry;
        int woff = (wid > 0) ? wsum[wid - 1] : 0;
        int excl = carryv + woff + (isum - tot);
        if (i0 + 0 < n) { rp[i0 + 0] = excl;                cur[i0 + 0] = excl; }
        if (i0 + 1 < n) { rp[i0 + 1] = excl + v0;           cur[i0 + 1] = excl + v0; }
        if (i0 + 2 < n) { rp[i0 + 2] = excl + v0 + v1;      cur[i0 + 2] = excl + v0 + v1; }
        if (i0 + 3 < n) { rp[i0 + 3] = excl + v0 + v1 + v2; cur[i0 + 3] = excl + v0 + v1 + v2; }
        __syncthreads();
        if (tid == 0) carry = carryv + wsum[31];
        __syncthreads();
    }
    if (tid == 0) rp[n] = carry;
}

__global__ void scatter_kernel(const int* __restrict__ src1, const int* __restrict__ dst1,
                               const int* __restrict__ src2, const int* __restrict__ dst2) {
    int e = (blockIdx.x * blockDim.x + threadIdx.x) * 4;
    if (e < E1) {
        int4 s = *(const int4*)(src1 + e);
        int4 d = *(const int4*)(dst1 + e);
        int p;
        p = atomicAdd(&g_cur1[d.x], 1); g_csr1[p] = s.x;
        p = atomicAdd(&g_cur1[d.y], 1); g_csr1[p] = s.y;
        p = atomicAdd(&g_cur1[d.z], 1); g_csr1[p] = s.z;
        p = atomicAdd(&g_cur1[d.w], 1); g_csr1[p] = s.w;
    }
    if (e < E2) {
        int4 s = *(const int4*)(src2 + e);
        int4 d = *(const int4*)(dst2 + e);
        int p;
        p = atomicAdd(&g_cur2[d.x], 1); g_csr2[p] = s.x;
        p = atomicAdd(&g_cur2[d.y], 1); g_csr2[p] = s.y;
        p = atomicAdd(&g_cur2[d.z], 1); g_csr2[p] = s.z;
        p = atomicAdd(&g_cur2[d.w], 1); g_csr2[p] = s.w;
    }
}

__global__ void cvt_w_kernel(const float* __restrict__ W1l, const float* __restrict__ W1r,
                             const float* __restrict__ W2l, const float* __restrict__ W2r) {
    int i = blockIdx.x * blockDim.x + threadIdx.x;
    if (i < 128 * 256) {
        int k = i >> 8, n = i & 255;
        g_w1lt[n * 128 + k] = __float2half(W1l[i]);
        g_w1rt[n * 128 + k] = __float2half(W1r[i]);
    }
    if (i < 256 * 64) {
        int k = i >> 6, n = i & 63;
        g_w2lt[n * 256 + k] = __float2half(W2l[i]);
        g_w2rt[n * 256 + k] = __float2half(W2r[i]);
    }
}

// ---------------- mma + ldmatrix helpers ----------------
__device__ __forceinline__ void mma_f16(float* d, const unsigned* a, const unsigned* b) {
    asm volatile("mma.sync.aligned.m16n8k16.row.col.f32.f16.f16.f32 "
        "{%0,%1,%2,%3}, {%4,%5,%6,%7}, {%8,%9}, {%0,%1,%2,%3};"
        : "+f"(d[0]), "+f"(d[1]), "+f"(d[2]), "+f"(d[3])
        : "r"(a[0]), "r"(a[1]), "r"(a[2]), "r"(a[3]), "r"(b[0]), "r"(b[1]));
}

__device__ __forceinline__ void ldsm_x4(unsigned& r0, unsigned& r1, unsigned& r2, unsigned& r3,
                                        unsigned addr) {
    asm volatile("ldmatrix.sync.aligned.m8n8.x4.shared.b16 {%0,%1,%2,%3}, [%4];"
        : "=r"(r0), "=r"(r1), "=r"(r2), "=r"(r3) : "r"(addr));
}

__device__ __forceinline__ uint4 pack_f8_to_h8(float4 v0, float4 v1) {
    __half2 h0 = __floats2half2_rn(v0.x, v0.y);
    __half2 h1 = __floats2half2_rn(v0.z, v0.w);
    __half2 h2 = __floats2half2_rn(v1.x, v1.y);
    __half2 h3 = __floats2half2_rn(v1.z, v1.w);
    uint4 u;
    u.x = *(unsigned*)&h0; u.y = *(unsigned*)&h1;
    u.z = *(unsigned*)&h2; u.w = *(unsigned*)&h3;
    return u;
}

// ---------------- layer-1 GEMM: C[M,256] = A_fp32[M,128] @ Bt[256,128]^T + bias ----------------
// BM=64, full N=256, BK=32, 256 threads (8 warps: 2M x 4N), warp tile 32x64.
__global__ __launch_bounds__(256, 2) void gemm_f16_l1(
    const float* __restrict__ A, const __half* __restrict__ Bt,
    const float* __restrict__ bias, void* __restrict__ Cout,
    int M, int out_half)
{
    __shared__ __half As[64][40];
    __shared__ __half Bs[256][40];
    const int K = 128;
    int tid = threadIdx.x;
    int lane = tid & 31, warp = tid >> 5;
    int wm = warp & 1, wn = warp >> 1;
    int g = lane >> 2, t = lane & 3;
    int bm = blockIdx.x * 64;

    int arow = tid >> 2, aseg = (tid & 3) * 8;

    unsigned asBase = (unsigned)__cvta_generic_to_shared(&As[0][0]);
    unsigned bsBase = (unsigned)__cvta_generic_to_shared(&Bs[0][0]);
    unsigned aAddr[2];
    #pragma unroll
    for (int mi = 0; mi < 2; mi++)
        aAddr[mi] = asBase + (unsigned)((wm * 32 + mi * 16 + (lane & 15)) * 80 + ((lane >> 4) * 8) * 2);
    unsigned bAddr[4];
    #pragma unroll
    for (int p = 0; p < 4; p++)
        bAddr[p] = bsBase + (unsigned)((wn * 64 + p * 16 + ((lane >> 4) << 3) + (lane & 7)) * 80
                                       + (((lane >> 3) & 1) * 8) * 2);

    float acc[2][8][4];
    #pragma unroll
    for (int mi = 0; mi < 2; mi++)
        #pragma unroll
        for (int ni = 0; ni < 8; ni++)
            #pragma unroll
            for (int j = 0; j < 4; j++) acc[mi][ni][j] = 0.f;

    float4 va0 = make_float4(0.f, 0.f, 0.f, 0.f), va1 = va0;
    uint4 vb[4];
    {
        int gr = bm + arow;
        if (gr < M) {
            const float* ap = A + (size_t)gr * K + aseg;
            va0 = *(const float4*)ap;
            va1 = *(const float4*)(ap + 4);
        }
        #pragma unroll
        for (int p = 0; p < 4; p++) {
            int idx = tid + p * 256;
            vb[p] = *(const uint4*)(Bt + (size_t)(idx >> 2) * K + (idx & 3) * 8);
        }
    }

    for (int k0 = 0; k0 < K; k0 += 32) {
        *(uint4*)&As[arow][aseg] = pack_f8_to_h8(va0, va1);
        #pragma unroll
        for (int p = 0; p < 4; p++) {
            int idx = tid + p * 256;
            *(uint4*)&Bs[idx >> 2][(idx & 3) * 8] = vb[p];
        }
        __syncthreads();

        if (k0 + 32 < K) {
            int gr = bm + arow;
            va0 = make_float4(0.f, 0.f, 0.f, 0.f); va1 = va0;
            if (gr < M) {
                const float* ap = A + (size_t)gr * K + k0 + 32 + aseg;
                va0 = *(const float4*)ap;
                va1 = *(const float4*)(ap + 4);
            }
            #pragma unroll
            for (int p = 0; p < 4; p++) {
                int idx = tid + p * 256;
                vb[p] = *(const uint4*)(Bt + (size_t)(idx >> 2) * K + k0 + 32 + (idx & 3) * 8);
            }
        }

        #pragma unroll
        for (int kk = 0; kk < 32; kk += 16) {
            unsigned af[2][4], bf[8][2];
            #pragma unroll
            for (int mi = 0; mi < 2; mi++)
                ldsm_x4(af[mi][0], af[mi][1], af[mi][2], af[mi][3], aAddr[mi] + kk * 2);
            #pragma unroll
            for (int p = 0; p < 4; p++)
                ldsm_x4(bf[2 * p][0], bf[2 * p][1], bf[2 * p + 1][0], bf[2 * p + 1][1],
                        bAddr[p] + kk * 2);
            #pragma unroll
            for (int mi = 0; mi < 2; mi++)
                #pragma unroll
                for (int ni = 0; ni < 8; ni++)
                    mma_f16(acc[mi][ni], af[mi], bf[ni]);
        }
        __syncthreads();
    }

    #pragma unroll
    for (int mi = 0; mi < 2; mi++) {
        #pragma unroll
        for (int ni = 0; ni < 8; ni++) {
            int col = wn * 64 + ni * 8 + 2 * t;
            float2 bb = *(const float2*)(bias + col);
            int r0 = bm + wm * 32 + mi * 16 + g;
            int r1 = r0 + 8;
            if (out_half) {
                __half* C = (__half*)Cout;
                if (r0 < M)
                    *(__half2*)(C + (size_t)r0 * 256 + col) =
                        __floats2half2_rn(acc[mi][ni][0] + bb.x, acc[mi][ni][1] + bb.y);
                if (r1 < M)
                    *(__half2*)(C + (size_t)r1 * 256 + col) =
                        __floats2half2_rn(acc[mi][ni][2] + bb.x, acc[mi][ni][3] + bb.y);
            } else {
                float* C = (float*)Cout;
                if (r0 < M)
                    *(float2*)(C + (size_t)r0 * 256 + col) =
                        make_float2(acc[mi][ni][0] + bb.x, acc[mi][ni][1] + bb.y);
                if (r1 < M)
                    *(float2*)(C + (size_t)r1 * 256 + col) =
                        make_float2(acc[mi][ni][2] + bb.x, acc[mi][ni][3] + bb.y);
            }
        }
    }
}

// ---------------- layer-2 GEMM: C[M,64] = relu(bn(Ah[M,256])) @ Bt[64,256]^T + bias ----------------
// A is fp16 (g_hh); BN+ReLU applied during staging.
__global__ __launch_bounds__(256) void gemm_f16_l2(
    const __half* __restrict__ A, const __half* __restrict__ Bt,
    const float* __restrict__ bias, float* __restrict__ C, int M)
{
    __shared__ __half As[128][40];
    __shared__ __half Bs[64][40];
    const int K = 256;
    int tid = threadIdx.x;
    int lane = tid & 31, warp = tid >> 5;
    int wm = warp & 3, wn = warp >> 2;
    int g = lane >> 2, t = lane & 3;
    int bm = blockIdx.x * 128;

    unsigned asBase = (unsigned)__cvta_generic_to_shared(&As[0][0]);
    unsigned bsBase = (unsigned)__cvta_generic_to_shared(&Bs[0][0]);
    unsigned aAddr[2];
    #pragma unroll
    for (int mi = 0; mi < 2; mi++)
        aAddr[mi] = asBase + (unsigned)((wm * 32 + mi * 16 + (lane & 15)) * 80 + ((lane >> 4) * 8) * 2);
    unsigned bAddr[2];
    #pragma unroll
    for (int p = 0; p < 2; p++)
        bAddr[p] = bsBase + (unsigned)((wn * 32 + p * 16 + ((lane >> 4) << 3) + (lane & 7)) * 80
                                       + (((lane >> 3) & 1) * 8) * 2);

    float acc[2][4][4];
    #pragma unroll
    for (int mi = 0; mi < 2; mi++)
        #pragma unroll
        for (int ni = 0; ni < 4; ni++)
            #pragma unroll
            for (int j = 0; j < 4; j++) acc[mi][ni][j] = 0.f;

    for (int k0 = 0; k0 < K; k0 += 32) {
        // A tile 128 rows x 32 halves = 512 uint4 segments -> 2 passes of 256 threads
        #pragma unroll
        for (int p = 0; p < 2; p++) {
            int idx = tid + p * 256;          // 0..511
            int row = idx >> 2;               // 0..127
            int segq = (idx & 3) * 8;         // 0,8,16,24
            int gr = bm + row;
            uint4 raw = make_uint4(0u, 0u, 0u, 0u);
            if (gr < M) raw = *(const uint4*)(A + (size_t)gr * K + k0 + segq);
            float f[8]; unpack8(raw, f);
            float4 sc0 = *(const float4*)(g_bn_scale + k0 + segq);
            float4 sc1 = *(const float4*)(g_bn_scale + k0 + segq + 4);
            float4 sh0 = *(const float4*)(g_bn_shift + k0 + segq);
            float4 sh1 = *(const float4*)(g_bn_shift + k0 + segq + 4);
            float4 v0 = make_float4(fmaxf(f[0] * sc0.x + sh0.x, 0.f),
                                    fmaxf(f[1] * sc0.y + sh0.y, 0.f),
                                    fmaxf(f[2] * sc0.z + sh0.z, 0.f),
                                    fmaxf(f[3] * sc0.w + sh0.w, 0.f));
            float4 v1 = make_float4(fmaxf(f[4] * sc1.x + sh1.x, 0.f),
                                    fmaxf(f[5] * sc1.y + sh1.y, 0.f),
                                    fmaxf(f[6] * sc1.z + sh1.z, 0.f),
                                    fmaxf(f[7] * sc1.w + sh1.w, 0.f));
            *(uint4*)&As[row][segq] = pack_f8_to_h8(v0, v1);
        }
        {
            int row = tid >> 2, seg = (tid & 3) * 8;
            *(uint4*)&Bs[row][seg] = *(const uint4*)(Bt + (size_t)row * K + k0 + seg);
        }
        __syncthreads();
        #pragma unroll
        for (int kk = 0; kk < 32; kk += 16) {
            unsigned af[2][4], bf[4][2];
            #pragma unroll
            for (int mi = 0; mi < 2; mi++)
                ldsm_x4(af[mi][0], af[mi][1], af[mi][2], af[mi][3], aAddr[mi] + kk * 2);
            #pragma unroll
            for (int p = 0; p < 2; p++)
                ldsm_x4(bf[2 * p][0], bf[2 * p][1], bf[2 * p + 1][0], bf[2 * p + 1][1],
                        bAddr[p] + kk * 2);
            #pragma unroll
            for (int mi = 0; mi < 2; mi++)
                #pragma unroll
                for (int ni = 0; ni < 4; ni++)
                    mma_f16(acc[mi][ni], af[mi], bf[ni]);
        }
        __syncthreads();
    }

    #pragma unroll
    for (int mi = 0; mi < 2; mi++) {
        #pragma unroll
        for (int ni = 0; ni < 4; ni++) {
            int col = wn * 32 + ni * 8 + 2 * t;
            float2 bb = *(const float2*)(bias + col);
            int r0 = bm + wm * 32 + mi * 16 + g;
            int r1 = r0 + 8;
            if (r0 < M)
                *(float2*)(C + (size_t)r0 * 64 + col) =
                    make_float2(acc[mi][ni][0] + bb.x, acc[mi][ni][1] + bb.y);
            if (r1 < M)
                *(float2*)(C + (size_t)r1 * 64 + col) =
                    make_float2(acc[mi][ni][2] + bb.x, acc[mi][ni][3] + bb.y);
        }
    }
}

// ---------------- layer-1 fused edge kernel: 8-edge gather groups, online softmax ----------------
__global__ __launch_bounds__(256) void edge1_kernel(const float* __restrict__ att,
                                                    const float* __restrict__ bias)
{
    int w = (blockIdx.x * 256 + threadIdx.x) >> 5;
    int lane = threadIdx.x & 31;
    if (w >= N2) return;
    int off = lane * 8;

    float xr[8], at[8];
    {
        const float* xrp = g_xr1 + (size_t)w * D1 + off;
        float4 a = *(const float4*)xrp, b = *(const float4*)(xrp + 4);
        xr[0] = a.x; xr[1] = a.y; xr[2] = a.z; xr[3] = a.w;
        xr[4] = b.x; xr[5] = b.y; xr[6] = b.z; xr[7] = b.w;
        float4 c = *(const float4*)(att + off), d = *(const float4*)(att + off + 4);
        at[0] = c.x; at[1] = c.y; at[2] = c.z; at[3] = c.w;
        at[4] = d.x; at[5] = d.y; at[6] = d.z; at[7] = d.w;
    }

    float m = -INFINITY, s = 0.f;
    float ac[8] = {0.f, 0.f, 0.f, 0.f, 0.f, 0.f, 0.f, 0.f};

    int jb = g_rp1[w], je = g_rp1[w + 1];
    int j = jb;

    for (; j + 8 <= je; j += 8) {
        uint4 rr[8];
        #pragma unroll
        for (int q = 0; q < 8; q++) {
            int src = __ldg(g_csr1 + j + q);
            rr[q] = __ldg((const uint4*)(g_xl1h + (size_t)src * D1 + off));
        }
        float p[8];
        #pragma unroll
        for (int q = 0; q < 8; q++) {
            float f[8]; unpack8(rr[q], f);
            float pp = 0.f;
            #pragma unroll
            for (int c = 0; c < 8; c++) pp += lrelu(f[c] + xr[c]) * at[c];
            pp += __shfl_xor_sync(FULLM, pp, 1);
            pp += __shfl_xor_sync(FULLM, pp, 2);
            pp += __shfl_xor_sync(FULLM, pp, 4);
            p[q] = pp;
        }
        float nm = m;
        #pragma unroll
        for (int q = 0; q < 8; q++) nm = fmaxf(nm, p[q]);
        float sc = __expf(m - nm);
        float wq[8], ssum = 0.f;
        #pragma unroll
        for (int q = 0; q < 8; q++) { wq[q] = __expf(p[q] - nm); ssum += wq[q]; }
        s = s * sc + ssum;
        #pragma unroll
        for (int c = 0; c < 8; c++) ac[c] *= sc;
        #pragma unroll
        for (int q = 0; q < 8; q++) {
            float f[8]; unpack8(rr[q], f);
            #pragma unroll
            for (int c = 0; c < 8; c++) ac[c] += wq[q] * f[c];
        }
        m = nm;
    }

    for (; j + 4 <= je; j += 4) {
        uint4 rr[4];
        #pragma unroll
        for (int q = 0; q < 4; q++) {
            int src = __ldg(g_csr1 + j + q);
            rr[q] = __ldg((const uint4*)(g_xl1h + (size_t)src * D1 + off));
        }
        float p[4];
        #pragma unroll
        for (int q = 0; q < 4; q++) {
            float f[8]; unpack8(rr[q], f);
            float pp = 0.f;
            #pragma unroll
            for (int c = 0; c < 8; c++) pp += lrelu(f[c] + xr[c]) * at[c];
            pp += __shfl_xor_sync(FULLM, pp, 1);
            pp += __shfl_xor_sync(FULLM, pp, 2);
            pp += __shfl_xor_sync(FULLM, pp, 4);
            p[q] = pp;
        }
        float nm = fmaxf(fmaxf(fmaxf(p[0], p[1]), fmaxf(p[2], p[3])), m);
        float sc = __expf(m - nm);
        float wq[4], ssum = 0.f;
        #pragma unroll
        for (int q = 0; q < 4; q++) { wq[q] = __expf(p[q] - nm); ssum += wq[q]; }
        s = s * sc + ssum;
        #pragma unroll
        for (int c = 0; c < 8; c++) ac[c] *= sc;
        #pragma unroll
        for (int q = 0; q < 4; q++) {
            float f[8]; unpack8(rr[q], f);
            #pragma unroll
            for (int c = 0; c < 8; c++) ac[c] += wq[q] * f[c];
        }
        m = nm;
    }

    for (; j < je; ++j) {
        int src = __ldg(g_csr1 + j);
        uint4 raw = __ldg((const uint4*)(g_xl1h + (size_t)src * D1 + off));
        float f[8]; unpack8(raw, f);
        float pp = 0.f;
        #pragma unroll
        for (int c = 0; c < 8; c++) pp += lrelu(f[c] + xr[c]) * at[c];
        pp += __shfl_xor_sync(FULLM, pp, 1);
        pp += __shfl_xor_sync(FULLM, pp, 2);
        pp += __shfl_xor_sync(FULLM, pp, 4);
        float nm = fmaxf(m, pp);
        float sc = __expf(m - nm);
        float wg = __expf(pp - nm);
        s = s * sc + wg;
        #pragma unroll
        for (int c = 0; c < 8; c++) ac[c] = ac[c] * sc + wg * f[c];
        m = nm;
    }

    float inv = 1.f / (s + SM_EPS);
    float o[8];
    {
        float4 bA = *(const float4*)(bias + off);
        float4 bB = *(const float4*)(bias + off + 4);
        o[0] = ac[0] * inv + bA.x; o[1] = ac[1] * inv + bA.y;
        o[2] = ac[2] * inv + bA.z; o[3] = ac[3] * inv + bA.w;
        o[4] = ac[4] * inv + bB.x; o[5] = ac[5] * inv + bB.y;
        o[6] = ac[6] * inv + bB.z; o[7] = ac[7] * inv + bB.w;
    }

    uint4 packed = pack_f8_to_h8(make_float4(o[0], o[1], o[2], o[3]),
                                 make_float4(o[4], o[5], o[6], o[7]));
    *(uint4*)(g_hh + (size_t)w * D1 + off) = packed;
}

// ---------------- batchnorm statistics (low-contention pass over fp16 g_hh) ----------------
__global__ void bn_stats_kernel() {
    int col = threadIdx.x;   // 256 threads, one column each
    float s = 0.f, q = 0.f;
    for (int r = blockIdx.x; r < N2; r += gridDim.x) {
        float v = __half2float(g_hh[(size_t)r * D1 + col]);
        s += v;
        q += v * v;
    }
    atomicAdd(&g_bn_sum[col], s);    // 256 arrivals per address (gridDim=256)
    atomicAdd(&g_bn_sqs[col], q);
}
__global__ void bn_final_kernel(const float* __restrict__ gamma, const float* __restrict__ beta) {
    int c = threadIdx.x;
    float mu = g_bn_sum[c] * (1.f / N2);
    float var = g_bn_sqs[c] * (1.f / N2) - mu * mu;
    var = fmaxf(var, 0.f);
    float sc = gamma[c] * rsqrtf(var + BN_EPS);
    g_bn_scale[c] = sc;
    g_bn_shift[c] = beta[c] - mu * sc;
}

// ---------------- layer-2 fused edge kernel + log_softmax ----------------
__global__ __launch_bounds__(256) void edge2_kernel(const float* __restrict__ att,
                                                    const float* __restrict__ bias,
                                                    float* __restrict__ out)
{
    int w = (blockIdx.x * 256 + threadIdx.x) >> 5;
    int lane = threadIdx.x & 31;
    if (w >= N3) return;
    int off = lane * 2;

    float2 xr = *(const float2*)(g_xr2 + (size_t)w * D2 + off);
    float2 at = *(const float2*)(att + off);
    float m = -INFINITY, s = 0.f, a0 = 0.f, a1 = 0.f;

    int jb = g_rp2[w], je = g_rp2[w + 1];
    for (int j = jb; j < je; ++j) {
        int src = g_csr2[j];
        float2 xj = *(const float2*)(g_xl2 + (size_t)src * D2 + off);
        float p = lrelu(xj.x + xr.x) * at.x + lrelu(xj.y + xr.y) * at.y;
        #pragma unroll
        for (int o = 16; o > 0; o >>= 1) p += __shfl_xor_sync(FULLM, p, o);
        float nm = fmaxf(m, p);
        float sc = __expf(m - nm);
        float wg = __expf(p - nm);
        s = s * sc + wg;
        a0 = a0 * sc + wg * xj.x;
        a1 = a1 * sc + wg * xj.y;
        m = nm;
    }
    float inv = 1.f / (s + SM_EPS);
    float o0 = a0 * inv + bias[off];
    float o1 = a1 * inv + bias[off + 1];

    float mx = fmaxf(o0, o1);
    #pragma unroll
    for (int o = 16; o > 0; o >>= 1) mx = fmaxf(mx, __shfl_xor_sync(FULLM, mx, o));
    float se = __expf(o0 - mx) + __expf(o1 - mx);
    #pragma unroll
    for (int o = 16; o > 0; o >>= 1) se += __shfl_xor_sync(FULLM, se, o);
    float lse = __logf(se);
    float2 r = make_float2(o0 - mx - lse, o1 - mx - lse);
    *(float2*)(out + (size_t)w * D2 + off) = r;
}

// ---------------- launch ----------------
extern "C" void kernel_launch(void* const* d_in, const int* in_sizes, int n_in,
                              void* d_out, int out_size)
{
    const float* x       = (const float*)d_in[0];
    const int*   ei1_src = (const int*)d_in[1];
    const int*   ei1_dst = (const int*)d_in[2];
    const int*   ei2_src = (const int*)d_in[3];
    const int*   ei2_dst = (const int*)d_in[4];
    const float* W1l     = (const float*)d_in[5];
    const float* b1l     = (const float*)d_in[6];
    const float* W1r     = (const float*)d_in[7];
    const float* b1r     = (const float*)d_in[8];
    const float* att1    = (const float*)d_in[9];
    const float* bias1   = (const float*)d_in[10];
    const float* gamma   = (const float*)d_in[11];
    const float* beta    = (const float*)d_in[12];
    const float* W2l     = (const float*)d_in[13];
    const float* b2l     = (const float*)d_in[14];
    const float* W2r     = (const float*)d_in[15];
    const float* b2r     = (const float*)d_in[16];
    const float* att2    = (const float*)d_in[17];
    const float* bias2   = (const float*)d_in[18];
    float* out = (float*)d_out;

    __half *p_xl1h, *p_hh, *p_w1lt, *p_w1rt, *p_w2lt, *p_w2rt;
    float *p_xr1, *p_xl2, *p_xr2;
    cudaGetSymbolAddress((void**)&p_xl1h, g_xl1h);
    cudaGetSymbolAddress((void**)&p_hh,   g_hh);
    cudaGetSymbolAddress((void**)&p_w1lt, g_w1lt);
    cudaGetSymbolAddress((void**)&p_w1rt, g_w1rt);
    cudaGetSymbolAddress((void**)&p_w2lt, g_w2lt);
    cudaGetSymbolAddress((void**)&p_w2rt, g_w2rt);
    cudaGetSymbolAddress((void**)&p_xr1, g_xr1);
    cudaGetSymbolAddress((void**)&p_xl2, g_xl2);
    cudaGetSymbolAddress((void**)&p_xr2, g_xr2);

    // fork side stream for the CSR chain (capturable event-fork pattern)
    cudaStream_t s2;
    cudaStreamCreateWithFlags(&s2, cudaStreamNonBlocking);
    cudaEvent_t evF, evJ;
    cudaEventCreateWithFlags(&evF, cudaEventDisableTiming);
    cudaEventCreateWithFlags(&evJ, cudaEventDisableTiming);

    cudaEventRecord(evF, 0);
    cudaStreamWaitEvent(s2, evF, 0);

    // Submission order keeps gemm_f16_l1(N1) as the 4th kernel for ncu capture.
    zero_kernel<<<(N2 + 255) / 256, 256, 0, s2>>>();
    hist_kernel<<<(E1 / 4 + 255) / 256, 256, 0, s2>>>(ei1_dst, ei2_dst);

    cvt_w_kernel<<<(128 * 256 + 255) / 256, 256>>>(W1l, W1r, W2l, W2r);
    gemm_f16_l1<<<N1 / 64, 256>>>(x, p_w1lt, b1l, p_xl1h, N1, 1);

    scan2_kernel<<<2, 1024, 0, s2>>>();
    scatter_kernel<<<(E1 / 4 + 255) / 256, 256, 0, s2>>>(ei1_src, ei1_dst, ei2_src, ei2_dst);
    cudaEventRecord(evJ, s2);

    gemm_f16_l1<<<(N2 + 63) / 64, 256>>>(x, p_w1rt, b1r, p_xr1, N2, 0);

    cudaStreamWaitEvent(0, evJ, 0);

    edge1_kernel<<<(N2 * 32 + 255) / 256, 256>>>(att1, bias1);

    bn_stats_kernel<<<256, 256>>>();
    bn_final_kernel<<<1, 256>>>(gamma, beta);

    gemm_f16_l2<<<(N2 + 127) / 128, 256>>>(p_hh, p_w2lt, b2l, p_xl2, N2);
    gemm_f16_l2<<<(N3 + 127) / 128, 256>>>(p_hh, p_w2rt, b2r, p_xr2, N3);

    edge2_kernel<<<(N3 * 32 + 255) / 256, 256>>>(att2, bias2, out);
}

// round 17
// speedup vs baseline: 9.4086x; 1.0290x over previous
#include <cuda_runtime.h>
#include <cuda_bf16.h>
#include <cuda_fp16.h>
#include <math.h>

// ---------------- problem constants ----------------
#define N1 160000
#define N2 40000
#define N3 10000
#define E1 800000
#define E2 200000
#define D1 256          // H1*HID
#define D2 64           // OUT
#define NEG_SLOPE 0.2f
#define BN_EPS 1e-5f
#define SM_EPS 1e-16f
#define FULLM 0xFFFFFFFFu

#define NB1 (N1 / 64)   // 2500 blocks, segment 1 of merged l1 gemm
#define NB1B (N2 / 64)  // 625 blocks, segment 2
#define NB2 ((N2 + 127) / 128)  // 313 blocks, segment 1 of merged l2 gemm
#define NB3 ((N3 + 127) / 128)  // 79 blocks, segment 2

// ---------------- device scratch (allocation-free) ----------------
__device__ __half g_xl1h[(size_t)N1 * D1];   // 82 MB  fp16 gather table
__device__ __half g_xr1h[(size_t)N2 * D1];   // 20.5 MB fp16
__device__ __half g_hh [(size_t)N2 * D1];    // 20.5 MB (layer1 out, fp16, pre-BN)
__device__ float  g_xl2[(size_t)N2 * D2];    // 10.2 MB
__device__ float  g_xr2[(size_t)N3 * D2];    // 2.6 MB

__device__ __half g_w1lt[D1 * 128];          // [N=256][K=128]
__device__ __half g_w1rt[D1 * 128];
__device__ __half g_w2lt[D2 * D1];           // [N=64][K=256]
__device__ __half g_w2rt[D2 * D1];

__device__ int g_cnt1[N2];
__device__ int g_rp1 [N2 + 1];
__device__ int g_cur1[N2];
__device__ int g_csr1[E1];

__device__ int g_cnt2[N3];
__device__ int g_rp2 [N3 + 1];
__device__ int g_cur2[N3];
__device__ int g_csr2[E2];

__device__ float g_bn_sum[D1];
__device__ float g_bn_sqs[D1];
__device__ float g_bn_scale[D1];
__device__ float g_bn_shift[D1];

__device__ __forceinline__ float lrelu(float v) { return v > 0.f ? v : NEG_SLOPE * v; }

__device__ __forceinline__ void unpack8(uint4 r, float* f) {
    float2 a = __half22float2(*reinterpret_cast<const __half2*>(&r.x));
    float2 b = __half22float2(*reinterpret_cast<const __half2*>(&r.y));
    float2 c = __half22float2(*reinterpret_cast<const __half2*>(&r.z));
    float2 d = __half22float2(*reinterpret_cast<const __half2*>(&r.w));
    f[0] = a.x; f[1] = a.y; f[2] = b.x; f[3] = b.y;
    f[4] = c.x; f[5] = c.y; f[6] = d.x; f[7] = d.y;
}

// ---------------- CSR build ----------------
__global__ void zero_kernel() {
    int i = blockIdx.x * blockDim.x + threadIdx.x;
    if (i < N2) g_cnt1[i] = 0;
    if (i < N3) g_cnt2[i] = 0;
    if (i < D1) { g_bn_sum[i] = 0.f; g_bn_sqs[i] = 0.f; }
}

__global__ void hist_kernel(const int* __restrict__ d1, const int* __restrict__ d2) {
    int i = (blockIdx.x * blockDim.x + threadIdx.x) * 4;
    if (i < E1) {
        int4 v = *(const int4*)(d1 + i);
        atomicAdd(&g_cnt1[v.x], 1); atomicAdd(&g_cnt1[v.y], 1);
        atomicAdd(&g_cnt1[v.z], 1); atomicAdd(&g_cnt1[v.w], 1);
    }
    if (i < E2) {
        int4 v = *(const int4*)(d2 + i);
        atomicAdd(&g_cnt2[v.x], 1); atomicAdd(&g_cnt2[v.y], 1);
        atomicAdd(&g_cnt2[v.z], 1); atomicAdd(&g_cnt2[v.w], 1);
    }
}

__global__ __launch_bounds__(1024) void scan2_kernel() {
    int which = blockIdx.x;
    const int* cnt = which ? g_cnt2 : g_cnt1;
    int* rp  = which ? g_rp2  : g_rp1;
    int* cur = which ? g_cur2 : g_cur1;
    int n    = which ? N3     : N2;

    __shared__ int wsum[32];
    __shared__ int carry;
    int tid = threadIdx.x;
    int lane = tid & 31, wid = tid >> 5;
    if (tid == 0) carry = 0;
    __syncthreads();

    for (int base = 0; base < n; base += 4096) {
        int i0 = base + tid * 4;
        int v0 = (i0 + 0 < n) ? cnt[i0 + 0] : 0;
        int v1 = (i0 + 1 < n) ? cnt[i0 + 1] : 0;
        int v2 = (i0 + 2 < n) ? cnt[i0 + 2] : 0;
        int v3 = (i0 + 3 < n) ? cnt[i0 + 3] : 0;
        int tot = v0 + v1 + v2 + v3;
        int isum = tot;
        #pragma unroll
        for (int off = 1; off < 32; off <<= 1) {
            int t = __shfl_up_sync(FULLM, isum, off);
            if (lane >= off) isum += t;
        }
        if (lane == 31) wsum[wid] = isum;
        __syncthreads();
        if (wid == 0) {
            int s = wsum[lane];
            #pragma unroll
            for (int off = 1; off < 32; off <<= 1) {
                int t = __shfl_up_sync(FULLM, s, off);
                if (lane >= off) s += t;
            }
            wsum[lane] = s;
        }
        __syncthreads();
        int carryv = carry;
        int woff = (wid > 0) ? wsum[wid - 1] : 0;
        int excl = carryv + woff + (isum - tot);
        if (i0 + 0 < n) { rp[i0 + 0] = excl;                cur[i0 + 0] = excl; }
        if (i0 + 1 < n) { rp[i0 + 1] = excl + v0;           cur[i0 + 1] = excl + v0; }
        if (i0 + 2 < n) { rp[i0 + 2] = excl + v0 + v1;      cur[i0 + 2] = excl + v0 + v1; }
        if (i0 + 3 < n) { rp[i0 + 3] = excl + v0 + v1 + v2; cur[i0 + 3] = excl + v0 + v1 + v2; }
        __syncthreads();
        if (tid == 0) carry = carryv + wsum[31];
        __syncthreads();
    }
    if (tid == 0) rp[n] = carry;
}

__global__ void scatter_kernel(const int* __restrict__ src1, const int* __restrict__ dst1,
                               const int* __restrict__ src2, const int* __restrict__ dst2) {
    int e = (blockIdx.x * blockDim.x + threadIdx.x) * 4;
    if (e < E1) {
        int4 s = *(const int4*)(src1 + e);
        int4 d = *(const int4*)(dst1 + e);
        int p;
        p = atomicAdd(&g_cur1[d.x], 1); g_csr1[p] = s.x;
        p = atomicAdd(&g_cur1[d.y], 1); g_csr1[p] = s.y;
        p = atomicAdd(&g_cur1[d.z], 1); g_csr1[p] = s.z;
        p = atomicAdd(&g_cur1[d.w], 1); g_csr1[p] = s.w;
    }
    if (e < E2) {
        int4 s = *(const int4*)(src2 + e);
        int4 d = *(const int4*)(dst2 + e);
        int p;
        p = atomicAdd(&g_cur2[d.x], 1); g_csr2[p] = s.x;
        p = atomicAdd(&g_cur2[d.y], 1); g_csr2[p] = s.y;
        p = atomicAdd(&g_cur2[d.z], 1); g_csr2[p] = s.z;
        p = atomicAdd(&g_cur2[d.w], 1); g_csr2[p] = s.w;
    }
}

__global__ void cvt_w_kernel(const float* __restrict__ W1l, const float* __restrict__ W1r,
                             const float* __restrict__ W2l, const float* __restrict__ W2r) {
    int i = blockIdx.x * blockDim.x + threadIdx.x;
    if (i < 128 * 256) {
        int k = i >> 8, n = i & 255;
        g_w1lt[n * 128 + k] = __float2half(W1l[i]);
        g_w1rt[n * 128 + k] = __float2half(W1r[i]);
    }
    if (i < 256 * 64) {
        int k = i >> 6, n = i & 63;
        g_w2lt[n * 256 + k] = __float2half(W2l[i]);
        g_w2rt[n * 256 + k] = __float2half(W2r[i]);
    }
}

// ---------------- mma + ldmatrix helpers ----------------
__device__ __forceinline__ void mma_f16(float* d, const unsigned* a, const unsigned* b) {
    asm volatile("mma.sync.aligned.m16n8k16.row.col.f32.f16.f16.f32 "
        "{%0,%1,%2,%3}, {%4,%5,%6,%7}, {%8,%9}, {%0,%1,%2,%3};"
        : "+f"(d[0]), "+f"(d[1]), "+f"(d[2]), "+f"(d[3])
        : "r"(a[0]), "r"(a[1]), "r"(a[2]), "r"(a[3]), "r"(b[0]), "r"(b[1]));
}

__device__ __forceinline__ void ldsm_x4(unsigned& r0, unsigned& r1, unsigned& r2, unsigned& r3,
                                        unsigned addr) {
    asm volatile("ldmatrix.sync.aligned.m8n8.x4.shared.b16 {%0,%1,%2,%3}, [%4];"
        : "=r"(r0), "=r"(r1), "=r"(r2), "=r"(r3) : "r"(addr));
}

__device__ __forceinline__ uint4 pack_f8_to_h8(float4 v0, float4 v1) {
    __half2 h0 = __floats2half2_rn(v0.x, v0.y);
    __half2 h1 = __floats2half2_rn(v0.z, v0.w);
    __half2 h2 = __floats2half2_rn(v1.x, v1.y);
    __half2 h3 = __floats2half2_rn(v1.z, v1.w);
    uint4 u;
    u.x = *(unsigned*)&h0; u.y = *(unsigned*)&h1;
    u.z = *(unsigned*)&h2; u.w = *(unsigned*)&h3;
    return u;
}

// ---------------- merged layer-1 GEMM: [xl1h | xr1h] = x @ {W1l,W1r}^T + bias ----------------
// grid = NB1 + NB1B. BM=64, N=256, BK=32, 256 threads (8 warps: 2M x 4N).
__global__ __launch_bounds__(256, 2) void gemm_l1(
    const float* __restrict__ A,
    const __half* __restrict__ Bt0, const __half* __restrict__ Bt1,
    const float* __restrict__ b0, const float* __restrict__ b1)
{
    __shared__ __half As[64][40];
    __shared__ __half Bs[256][40];
    const int K = 128;
    int blk = blockIdx.x;
    const __half* Bt; const float* bias; __half* C; int bm;
    if (blk < NB1) { Bt = Bt0; bias = b0; C = g_xl1h; bm = blk * 64; }
    else           { Bt = Bt1; bias = b1; C = g_xr1h; bm = (blk - NB1) * 64; }

    int tid = threadIdx.x;
    int lane = tid & 31, warp = tid >> 5;
    int wm = warp & 1, wn = warp >> 1;
    int g = lane >> 2, t = lane & 3;

    int arow = tid >> 2, aseg = (tid & 3) * 8;

    unsigned asBase = (unsigned)__cvta_generic_to_shared(&As[0][0]);
    unsigned bsBase = (unsigned)__cvta_generic_to_shared(&Bs[0][0]);
    unsigned aAddr[2];
    #pragma unroll
    for (int mi = 0; mi < 2; mi++)
        aAddr[mi] = asBase + (unsigned)((wm * 32 + mi * 16 + (lane & 15)) * 80 + ((lane >> 4) * 8) * 2);
    unsigned bAddr[4];
    #pragma unroll
    for (int p = 0; p < 4; p++)
        bAddr[p] = bsBase + (unsigned)((wn * 64 + p * 16 + ((lane >> 4) << 3) + (lane & 7)) * 80
                                       + (((lane >> 3) & 1) * 8) * 2);

    float acc[2][8][4];
    #pragma unroll
    for (int mi = 0; mi < 2; mi++)
        #pragma unroll
        for (int ni = 0; ni < 8; ni++)
            #pragma unroll
            for (int j = 0; j < 4; j++) acc[mi][ni][j] = 0.f;

    float4 va0, va1;
    uint4 vb[4];
    {
        const float* ap = A + (size_t)(bm + arow) * K + aseg;
        va0 = *(const float4*)ap;
        va1 = *(const float4*)(ap + 4);
        #pragma unroll
        for (int p = 0; p < 4; p++) {
            int idx = tid + p * 256;
            vb[p] = *(const uint4*)(Bt + (size_t)(idx >> 2) * K + (idx & 3) * 8);
        }
    }

    for (int k0 = 0; k0 < K; k0 += 32) {
        *(uint4*)&As[arow][aseg] = pack_f8_to_h8(va0, va1);
        #pragma unroll
        for (int p = 0; p < 4; p++) {
            int idx = tid + p * 256;
            *(uint4*)&Bs[idx >> 2][(idx & 3) * 8] = vb[p];
        }
        __syncthreads();

        if (k0 + 32 < K) {
            const float* ap = A + (size_t)(bm + arow) * K + k0 + 32 + aseg;
            va0 = *(const float4*)ap;
            va1 = *(const float4*)(ap + 4);
            #pragma unroll
            for (int p = 0; p < 4; p++) {
                int idx = tid + p * 256;
                vb[p] = *(const uint4*)(Bt + (size_t)(idx >> 2) * K + k0 + 32 + (idx & 3) * 8);
            }
        }

        #pragma unroll
        for (int kk = 0; kk < 32; kk += 16) {
            unsigned af[2][4], bf[8][2];
            #pragma unroll
            for (int mi = 0; mi < 2; mi++)
                ldsm_x4(af[mi][0], af[mi][1], af[mi][2], af[mi][3], aAddr[mi] + kk * 2);
            #pragma unroll
            for (int p = 0; p < 4; p++)
                ldsm_x4(bf[2 * p][0], bf[2 * p][1], bf[2 * p + 1][0], bf[2 * p + 1][1],
                        bAddr[p] + kk * 2);
            #pragma unroll
            for (int mi = 0; mi < 2; mi++)
                #pragma unroll
                for (int ni = 0; ni < 8; ni++)
                    mma_f16(acc[mi][ni], af[mi], bf[ni]);
        }
        __syncthreads();
    }

    #pragma unroll
    for (int mi = 0; mi < 2; mi++) {
        #pragma unroll
        for (int ni = 0; ni < 8; ni++) {
            int col = wn * 64 + ni * 8 + 2 * t;
            float2 bb = *(const float2*)(bias + col);
            int r0 = bm + wm * 32 + mi * 16 + g;
            *(__half2*)(C + (size_t)r0 * 256 + col) =
                __floats2half2_rn(acc[mi][ni][0] + bb.x, acc[mi][ni][1] + bb.y);
            *(__half2*)(C + (size_t)(r0 + 8) * 256 + col) =
                __floats2half2_rn(acc[mi][ni][2] + bb.x, acc[mi][ni][3] + bb.y);
        }
    }
}

// ---------------- merged layer-2 GEMM: {xl2,xr2} = relu(bn(hh)) @ {W2l,W2r}^T + bias ----------------
// grid = NB2 + NB3. BM=128, N=64, BK=32, 256 threads (8 warps: 4M x 2N).
__global__ __launch_bounds__(256) void gemm_l2(
    const __half* __restrict__ Bt0, const __half* __restrict__ Bt1,
    const float* __restrict__ b0, const float* __restrict__ b1)
{
    __shared__ __half As[128][40];
    __shared__ __half Bs[64][40];
    const int K = 256;
    int blk = blockIdx.x;
    const __half* Bt; const float* bias; float* C; int bm; int M;
    if (blk < NB2) { Bt = Bt0; bias = b0; C = g_xl2; bm = blk * 128; M = N2; }
    else           { Bt = Bt1; bias = b1; C = g_xr2; bm = (blk - NB2) * 128; M = N3; }
    const __half* A = g_hh;

    int tid = threadIdx.x;
    int lane = tid & 31, warp = tid >> 5;
    int wm = warp & 3, wn = warp >> 2;
    int g = lane >> 2, t = lane & 3;

    unsigned asBase = (unsigned)__cvta_generic_to_shared(&As[0][0]);
    unsigned bsBase = (unsigned)__cvta_generic_to_shared(&Bs[0][0]);
    unsigned aAddr[2];
    #pragma unroll
    for (int mi = 0; mi < 2; mi++)
        aAddr[mi] = asBase + (unsigned)((wm * 32 + mi * 16 + (lane & 15)) * 80 + ((lane >> 4) * 8) * 2);
    unsigned bAddr[2];
    #pragma unroll
    for (int p = 0; p < 2; p++)
        bAddr[p] = bsBase + (unsigned)((wn * 32 + p * 16 + ((lane >> 4) << 3) + (lane & 7)) * 80
                                       + (((lane >> 3) & 1) * 8) * 2);

    float acc[2][4][4];
    #pragma unroll
    for (int mi = 0; mi < 2; mi++)
        #pragma unroll
        for (int ni = 0; ni < 4; ni++)
            #pragma unroll
            for (int j = 0; j < 4; j++) acc[mi][ni][j] = 0.f;

    for (int k0 = 0; k0 < K; k0 += 32) {
        #pragma unroll
        for (int p = 0; p < 2; p++) {
            int idx = tid + p * 256;          // 0..511
            int row = idx >> 2;               // 0..127
            int segq = (idx & 3) * 8;
            int gr = bm + row;
            uint4 raw = make_uint4(0u, 0u, 0u, 0u);
            if (gr < M) raw = *(const uint4*)(A + (size_t)gr * K + k0 + segq);
            float f[8]; unpack8(raw, f);
            float4 sc0 = *(const float4*)(g_bn_scale + k0 + segq);
            float4 sc1 = *(const float4*)(g_bn_scale + k0 + segq + 4);
            float4 sh0 = *(const float4*)(g_bn_shift + k0 + segq);
            float4 sh1 = *(const float4*)(g_bn_shift + k0 + segq + 4);
            float4 v0 = make_float4(fmaxf(f[0] * sc0.x + sh0.x, 0.f),
                                    fmaxf(f[1] * sc0.y + sh0.y, 0.f),
                                    fmaxf(f[2] * sc0.z + sh0.z, 0.f),
                                    fmaxf(f[3] * sc0.w + sh0.w, 0.f));
            float4 v1 = make_float4(fmaxf(f[4] * sc1.x + sh1.x, 0.f),
                                    fmaxf(f[5] * sc1.y + sh1.y, 0.f),
                                    fmaxf(f[6] * sc1.z + sh1.z, 0.f),
                                    fmaxf(f[7] * sc1.w + sh1.w, 0.f));
            *(uint4*)&As[row][segq] = pack_f8_to_h8(v0, v1);
        }
        {
            int row = tid >> 2, seg = (tid & 3) * 8;
            *(uint4*)&Bs[row][seg] = *(const uint4*)(Bt + (size_t)row * K + k0 + seg);
        }
        __syncthreads();
        #pragma unroll
        for (int kk = 0; kk < 32; kk += 16) {
            unsigned af[2][4], bf[4][2];
            #pragma unroll
            for (int mi = 0; mi < 2; mi++)
                ldsm_x4(af[mi][0], af[mi][1], af[mi][2], af[mi][3], aAddr[mi] + kk * 2);
            #pragma unroll
            for (int p = 0; p < 2; p++)
                ldsm_x4(bf[2 * p][0], bf[2 * p][1], bf[2 * p + 1][0], bf[2 * p + 1][1],
                        bAddr[p] + kk * 2);
            #pragma unroll
            for (int mi = 0; mi < 2; mi++)
                #pragma unroll
                for (int ni = 0; ni < 4; ni++)
                    mma_f16(acc[mi][ni], af[mi], bf[ni]);
        }
        __syncthreads();
    }

    #pragma unroll
    for (int mi = 0; mi < 2; mi++) {
        #pragma unroll
        for (int ni = 0; ni < 4; ni++) {
            int col = wn * 32 + ni * 8 + 2 * t;
            float2 bb = *(const float2*)(bias + col);
            int r0 = bm + wm * 32 + mi * 16 + g;
            int r1 = r0 + 8;
            if (r0 < M)
                *(float2*)(C + (size_t)r0 * 64 + col) =
                    make_float2(acc[mi][ni][0] + bb.x, acc[mi][ni][1] + bb.y);
            if (r1 < M)
                *(float2*)(C + (size_t)r1 * 64 + col) =
                    make_float2(acc[mi][ni][2] + bb.x, acc[mi][ni][3] + bb.y);
        }
    }
}

// ---------------- layer-1 fused edge kernel: 8-edge gather groups, online softmax ----------------
__global__ __launch_bounds__(256) void edge1_kernel(const float* __restrict__ att,
                                                    const float* __restrict__ bias)
{
    int w = (blockIdx.x * 256 + threadIdx.x) >> 5;
    int lane = threadIdx.x & 31;
    if (w >= N2) return;
    int off = lane * 8;

    float xr[8], at[8];
    {
        uint4 rxr = *(const uint4*)(g_xr1h + (size_t)w * D1 + off);
        unpack8(rxr, xr);
        float4 c = *(const float4*)(att + off), d = *(const float4*)(att + off + 4);
        at[0] = c.x; at[1] = c.y; at[2] = c.z; at[3] = c.w;
        at[4] = d.x; at[5] = d.y; at[6] = d.z; at[7] = d.w;
    }

    float m = -INFINITY, s = 0.f;
    float ac[8] = {0.f, 0.f, 0.f, 0.f, 0.f, 0.f, 0.f, 0.f};

    int jb = g_rp1[w], je = g_rp1[w + 1];
    int j = jb;

    for (; j + 8 <= je; j += 8) {
        uint4 rr[8];
        #pragma unroll
        for (int q = 0; q < 8; q++) {
            int src = __ldg(g_csr1 + j + q);
            rr[q] = __ldg((const uint4*)(g_xl1h + (size_t)src * D1 + off));
        }
        float p[8];
        #pragma unroll
        for (int q = 0; q < 8; q++) {
            float f[8]; unpack8(rr[q], f);
            float pp = 0.f;
            #pragma unroll
            for (int c = 0; c < 8; c++) pp += lrelu(f[c] + xr[c]) * at[c];
            pp += __shfl_xor_sync(FULLM, pp, 1);
            pp += __shfl_xor_sync(FULLM, pp, 2);
            pp += __shfl_xor_sync(FULLM, pp, 4);
            p[q] = pp;
        }
        float nm = m;
        #pragma unroll
        for (int q = 0; q < 8; q++) nm = fmaxf(nm, p[q]);
        float sc = __expf(m - nm);
        float wq[8], ssum = 0.f;
        #pragma unroll
        for (int q = 0; q < 8; q++) { wq[q] = __expf(p[q] - nm); ssum += wq[q]; }
        s = s * sc + ssum;
        #pragma unroll
        for (int c = 0; c < 8; c++) ac[c] *= sc;
        #pragma unroll
        for (int q = 0; q < 8; q++) {
            float f[8]; unpack8(rr[q], f);
            #pragma unroll
            for (int c = 0; c < 8; c++) ac[c] += wq[q] * f[c];
        }
        m = nm;
    }

    for (; j + 4 <= je; j += 4) {
        uint4 rr[4];
        #pragma unroll
        for (int q = 0; q < 4; q++) {
            int src = __ldg(g_csr1 + j + q);
            rr[q] = __ldg((const uint4*)(g_xl1h + (size_t)src * D1 + off));
        }
        float p[4];
        #pragma unroll
        for (int q = 0; q < 4; q++) {
            float f[8]; unpack8(rr[q], f);
            float pp = 0.f;
            #pragma unroll
            for (int c = 0; c < 8; c++) pp += lrelu(f[c] + xr[c]) * at[c];
            pp += __shfl_xor_sync(FULLM, pp, 1);
            pp += __shfl_xor_sync(FULLM, pp, 2);
            pp += __shfl_xor_sync(FULLM, pp, 4);
            p[q] = pp;
        }
        float nm = fmaxf(fmaxf(fmaxf(p[0], p[1]), fmaxf(p[2], p[3])), m);
        float sc = __expf(m - nm);
        float wq[4], ssum = 0.f;
        #pragma unroll
        for (int q = 0; q < 4; q++) { wq[q] = __expf(p[q] - nm); ssum += wq[q]; }
        s = s * sc + ssum;
        #pragma unroll
        for (int c = 0; c < 8; c++) ac[c] *= sc;
        #pragma unroll
        for (int q = 0; q < 4; q++) {
            float f[8]; unpack8(rr[q], f);
            #pragma unroll
            for (int c = 0; c < 8; c++) ac[c] += wq[q] * f[c];
        }
        m = nm;
    }

    for (; j < je; ++j) {
        int src = __ldg(g_csr1 + j);
        uint4 raw = __ldg((const uint4*)(g_xl1h + (size_t)src * D1 + off));
        float f[8]; unpack8(raw, f);
        float pp = 0.f;
        #pragma unroll
        for (int c = 0; c < 8; c++) pp += lrelu(f[c] + xr[c]) * at[c];
        pp += __shfl_xor_sync(FULLM, pp, 1);
        pp += __shfl_xor_sync(FULLM, pp, 2);
        pp += __shfl_xor_sync(FULLM, pp, 4);
        float nm = fmaxf(m, pp);
        float sc = __expf(m - nm);
        float wg = __expf(pp - nm);
        s = s * sc + wg;
        #pragma unroll
        for (int c = 0; c < 8; c++) ac[c] = ac[c] * sc + wg * f[c];
        m = nm;
    }

    float inv = 1.f / (s + SM_EPS);
    float o[8];
    {
        float4 bA = *(const float4*)(bias + off);
        float4 bB = *(const float4*)(bias + off + 4);
        o[0] = ac[0] * inv + bA.x; o[1] = ac[1] * inv + bA.y;
        o[2] = ac[2] * inv + bA.z; o[3] = ac[3] * inv + bA.w;
        o[4] = ac[4] * inv + bB.x; o[5] = ac[5] * inv + bB.y;
        o[6] = ac[6] * inv + bB.z; o[7] = ac[7] * inv + bB.w;
    }

    uint4 packed = pack_f8_to_h8(make_float4(o[0], o[1], o[2], o[3]),
                                 make_float4(o[4], o[5], o[6], o[7]));
    *(uint4*)(g_hh + (size_t)w * D1 + off) = packed;
}

// ---------------- batchnorm statistics (low-contention pass over fp16 g_hh) ----------------
__global__ void bn_stats_kernel() {
    int col = threadIdx.x;   // 256 threads, one column each
    float s = 0.f, q = 0.f;
    for (int r = blockIdx.x; r < N2; r += gridDim.x) {
        float v = __half2float(g_hh[(size_t)r * D1 + col]);
        s += v;
        q += v * v;
    }
    atomicAdd(&g_bn_sum[col], s);    // 256 arrivals per address
    atomicAdd(&g_bn_sqs[col], q);
}
__global__ void bn_final_kernel(const float* __restrict__ gamma, const float* __restrict__ beta) {
    int c = threadIdx.x;
    float mu = g_bn_sum[c] * (1.f / N2);
    float var = g_bn_sqs[c] * (1.f / N2) - mu * mu;
    var = fmaxf(var, 0.f);
    float sc = gamma[c] * rsqrtf(var + BN_EPS);
    g_bn_scale[c] = sc;
    g_bn_shift[c] = beta[c] - mu * sc;
}

// ---------------- layer-2 fused edge kernel + log_softmax ----------------
__global__ __launch_bounds__(256) void edge2_kernel(const float* __restrict__ att,
                                                    const float* __restrict__ bias,
                                                    float* __restrict__ out)
{
    int w = (blockIdx.x * 256 + threadIdx.x) >> 5;
    int lane = threadIdx.x & 31;
    if (w >= N3) return;
    int off = lane * 2;

    float2 xr = *(const float2*)(g_xr2 + (size_t)w * D2 + off);
    float2 at = *(const float2*)(att + off);
    float m = -INFINITY, s = 0.f, a0 = 0.f, a1 = 0.f;

    int jb = g_rp2[w], je = g_rp2[w + 1];
    for (int j = jb; j < je; ++j) {
        int src = g_csr2[j];
        float2 xj = *(const float2*)(g_xl2 + (size_t)src * D2 + off);
        float p = lrelu(xj.x + xr.x) * at.x + lrelu(xj.y + xr.y) * at.y;
        #pragma unroll
        for (int o = 16; o > 0; o >>= 1) p += __shfl_xor_sync(FULLM, p, o);
        float nm = fmaxf(m, p);
        float sc = __expf(m - nm);
        float wg = __expf(p - nm);
        s = s * sc + wg;
        a0 = a0 * sc + wg * xj.x;
        a1 = a1 * sc + wg * xj.y;
        m = nm;
    }
    float inv = 1.f / (s + SM_EPS);
    float o0 = a0 * inv + bias[off];
    float o1 = a1 * inv + bias[off + 1];

    float mx = fmaxf(o0, o1);
    #pragma unroll
    for (int o = 16; o > 0; o >>= 1) mx = fmaxf(mx, __shfl_xor_sync(FULLM, mx, o));
    float se = __expf(o0 - mx) + __expf(o1 - mx);
    #pragma unroll
    for (int o = 16; o > 0; o >>= 1) se += __shfl_xor_sync(FULLM, se, o);
    float lse = __logf(se);
    float2 r = make_float2(o0 - mx - lse, o1 - mx - lse);
    *(float2*)(out + (size_t)w * D2 + off) = r;
}

// ---------------- launch ----------------
extern "C" void kernel_launch(void* const* d_in, const int* in_sizes, int n_in,
                              void* d_out, int out_size)
{
    const float* x       = (const float*)d_in[0];
    const int*   ei1_src = (const int*)d_in[1];
    const int*   ei1_dst = (const int*)d_in[2];
    const int*   ei2_src = (const int*)d_in[3];
    const int*   ei2_dst = (const int*)d_in[4];
    const float* W1l     = (const float*)d_in[5];
    const float* b1l     = (const float*)d_in[6];
    const float* W1r     = (const float*)d_in[7];
    const float* b1r     = (const float*)d_in[8];
    const float* att1    = (const float*)d_in[9];
    const float* bias1   = (const float*)d_in[10];
    const float* gamma   = (const float*)d_in[11];
    const float* beta    = (const float*)d_in[12];
    const float* W2l     = (const float*)d_in[13];
    const float* b2l     = (const float*)d_in[14];
    const float* W2r     = (const float*)d_in[15];
    const float* b2r     = (const float*)d_in[16];
    const float* att2    = (const float*)d_in[17];
    const float* bias2   = (const float*)d_in[18];
    float* out = (float*)d_out;

    __half *p_w1lt, *p_w1rt, *p_w2lt, *p_w2rt;
    cudaGetSymbolAddress((void**)&p_w1lt, g_w1lt);
    cudaGetSymbolAddress((void**)&p_w1rt, g_w1rt);
    cudaGetSymbolAddress((void**)&p_w2lt, g_w2lt);
    cudaGetSymbolAddress((void**)&p_w2rt, g_w2rt);

    // fork side stream for the CSR chain (capturable event-fork pattern)
    cudaStream_t s2;
    cudaStreamCreateWithFlags(&s2, cudaStreamNonBlocking);
    cudaEvent_t evF, evJ;
    cudaEventCreateWithFlags(&evF, cudaEventDisableTiming);
    cudaEventCreateWithFlags(&evJ, cudaEventDisableTiming);

    cudaEventRecord(evF, 0);
    cudaStreamWaitEvent(s2, evF, 0);

    // Submission order keeps gemm_l1 as the 4th kernel for ncu capture.
    zero_kernel<<<(N2 + 255) / 256, 256, 0, s2>>>();
    hist_kernel<<<(E1 / 4 + 255) / 256, 256, 0, s2>>>(ei1_dst, ei2_dst);

    cvt_w_kernel<<<(128 * 256 + 255) / 256, 256>>>(W1l, W1r, W2l, W2r);
    gemm_l1<<<NB1 + NB1B, 256>>>(x, p_w1lt, p_w1rt, b1l, b1r);   // merged: xl1h + xr1h

    scan2_kernel<<<2, 1024, 0, s2>>>();
    scatter_kernel<<<(E1 / 4 + 255) / 256, 256, 0, s2>>>(ei1_src, ei1_dst, ei2_src, ei2_dst);
    cudaEventRecord(evJ, s2);

    cudaStreamWaitEvent(0, evJ, 0);

    edge1_kernel<<<(N2 * 32 + 255) / 256, 256>>>(att1, bias1);

    bn_stats_kernel<<<256, 256>>>();
    bn_final_kernel<<<1, 256>>>(gamma, beta);

    gemm_l2<<<NB2 + NB3, 256>>>(p_w2lt, p_w2rt, b2l, b2r);       // merged: xl2 + xr2

    edge2_kernel<<<(N3 * 32 + 255) / 256, 256>>>(att2, bias2, out);
}